// round 1
// baseline (speedup 1.0000x reference)
#include <cuda_runtime.h>
#include <math.h>

// ---------------- problem constants ----------------
#define B_SZ   32768
#define D_M    256
#define CAT_D  1024

// ---------------- scratch layout (floats) ----------------
// weighted : B*4*256  = 33554432
// cat      : B*1024   = 33554432
// q        : B*256    =  8388608
// kv       : B*4*512  = 67108864
// ctx      : B*256    =  8388608
// attn_out : B*256    =  8388608
// h        : B*1024   = 33554432
// a_fc     : B*128    =  4194304
// f2       : B*512    = 16777216
#define W_OFF   0ull
#define CAT_OFF 33554432ull
#define Q_OFF   67108864ull
#define KV_OFF  75497472ull
#define CTX_OFF 142606336ull
#define AO_OFF  150994944ull
#define H_OFF   159383552ull
#define AFC_OFF 192937984ull
#define F2_OFF  197132288ull
#define SCR_TOTAL 213909504ull

__device__ float g_scratch[SCR_TOTAL];

__device__ __forceinline__ float gelu_exact(float x) {
    return 0.5f * x * (1.0f + erff(x * 0.70710678118654752440f));
}

// ---------------- kernel 1: weighted mix + cat[:,256:1024] ----------------
__global__ void prep_kernel(const float* __restrict__ w0, const float* __restrict__ w1,
                            const float* __restrict__ w2, const float* __restrict__ w3,
                            const float* __restrict__ tfw) {
    float t0 = tfw[0], t1 = tfw[1], t2 = tfw[2], t3 = tfw[3];
    float m = fmaxf(fmaxf(t0, t1), fmaxf(t2, t3));
    float e0 = expf(t0 - m), e1 = expf(t1 - m), e2 = expf(t2 - m), e3 = expf(t3 - m);
    float inv = 1.0f / (e0 + e1 + e2 + e3);
    float s[4] = {e0 * inv, e1 * inv, e2 * inv, e3 * inv};

    int g = blockIdx.x * blockDim.x + threadIdx.x;   // 0 .. B*64-1 (float4 granules)
    int b = g >> 6;
    int c = (g & 63) << 2;
    const float* ws[4] = {w0, w1, w2, w3};
    float* wt  = g_scratch + W_OFF;
    float* cat = g_scratch + CAT_OFF;
    size_t src = (size_t)b * D_M + c;
#pragma unroll
    for (int n = 0; n < 4; n++) {
        float4 v = *(const float4*)(ws[n] + src);
        v.x *= s[n]; v.y *= s[n]; v.z *= s[n]; v.w *= s[n];
        *(float4*)(wt + ((size_t)(b * 4 + n)) * D_M + c) = v;
        if (n >= 1)
            *(float4*)(cat + (size_t)b * CAT_D + n * D_M + c) = v;
    }
}

// ---------------- generic tiled SGEMM: C[M,N] = A[M,K] * W[N,K]^T + bias ----------------
// BM=BN=128, BK=16, 256 threads, 8x8 per-thread tile. All dims tile-divisible.
__global__ __launch_bounds__(256) void sgemm_nt(
    const float* __restrict__ A, int lda,
    const float* __restrict__ W,
    const float* __restrict__ bias,
    float* __restrict__ C,
    int N, int K, int gelu_epi)
{
    __shared__ float As[16][128];
    __shared__ float Ws[16][128];
    const int tid = threadIdx.x;
    const size_t bm = (size_t)blockIdx.y * 128;
    const int bn = blockIdx.x * 128;
    const int lr = tid >> 2;          // 0..63
    const int lc = (tid & 3) << 2;    // 0,4,8,12
    const int tm = (tid >> 4) << 3;   // 0..120
    const int tn = (tid & 15) << 3;   // 0..120

    const float* Ap0 = A + (bm + lr)      * (size_t)lda + lc;
    const float* Ap1 = A + (bm + lr + 64) * (size_t)lda + lc;
    const float* Wp0 = W + (size_t)(bn + lr)      * K + lc;
    const float* Wp1 = W + (size_t)(bn + lr + 64) * K + lc;

    float acc[8][8];
#pragma unroll
    for (int i = 0; i < 8; i++)
#pragma unroll
        for (int j = 0; j < 8; j++) acc[i][j] = 0.0f;

    for (int k0 = 0; k0 < K; k0 += 16) {
        float4 a0 = *(const float4*)(Ap0 + k0);
        float4 a1 = *(const float4*)(Ap1 + k0);
        float4 q0 = *(const float4*)(Wp0 + k0);
        float4 q1 = *(const float4*)(Wp1 + k0);
        As[lc + 0][lr] = a0.x; As[lc + 1][lr] = a0.y; As[lc + 2][lr] = a0.z; As[lc + 3][lr] = a0.w;
        As[lc + 0][lr + 64] = a1.x; As[lc + 1][lr + 64] = a1.y; As[lc + 2][lr + 64] = a1.z; As[lc + 3][lr + 64] = a1.w;
        Ws[lc + 0][lr] = q0.x; Ws[lc + 1][lr] = q0.y; Ws[lc + 2][lr] = q0.z; Ws[lc + 3][lr] = q0.w;
        Ws[lc + 0][lr + 64] = q1.x; Ws[lc + 1][lr + 64] = q1.y; Ws[lc + 2][lr + 64] = q1.z; Ws[lc + 3][lr + 64] = q1.w;
        __syncthreads();
#pragma unroll
        for (int kk = 0; kk < 16; kk++) {
            float a[8], b[8];
#pragma unroll
            for (int i = 0; i < 8; i++) a[i] = As[kk][tm + i];
#pragma unroll
            for (int j = 0; j < 8; j++) b[j] = Ws[kk][tn + j];
#pragma unroll
            for (int i = 0; i < 8; i++)
#pragma unroll
                for (int j = 0; j < 8; j++) acc[i][j] = fmaf(a[i], b[j], acc[i][j]);
        }
        __syncthreads();
    }

    float bv[8];
#pragma unroll
    for (int j = 0; j < 8; j++) bv[j] = bias[bn + tn + j];
#pragma unroll
    for (int i = 0; i < 8; i++) {
        float* Crow = C + (bm + tm + i) * (size_t)N + bn + tn;
        float v[8];
#pragma unroll
        for (int j = 0; j < 8; j++) {
            v[j] = acc[i][j] + bv[j];
            if (gelu_epi) v[j] = gelu_exact(v[j]);
        }
        float4 o0 = {v[0], v[1], v[2], v[3]};
        float4 o1 = {v[4], v[5], v[6], v[7]};
        *(float4*)(Crow)     = o0;
        *(float4*)(Crow + 4) = o1;
    }
}

// ---------------- kernel: tiny 4-token 4-head attention (one block per row) -------------
__global__ void attn_kernel() {
    const float* q  = g_scratch + Q_OFF;
    const float* kv = g_scratch + KV_OFF;
    float* ctx = g_scratch + CTX_OFF;
    int b = blockIdx.x, t = threadIdx.x, h = t >> 6;
    __shared__ float red[4][256];
    __shared__ float sc[16];
    __shared__ float aw[16];

    float qd = q[(size_t)b * 256 + t];
    const float* kvb = kv + (size_t)b * 2048;
    float vn[4];
#pragma unroll
    for (int n = 0; n < 4; n++) {
        float kn = kvb[n * 512 + t];
        vn[n] = kvb[n * 512 + 256 + t];
        red[n][t] = qd * kn;
    }
    __syncthreads();
    if (t < 16) {
        int hh = t >> 2, n = t & 3;
        float s = 0.0f;
        const float* r = &red[n][hh * 64];
#pragma unroll
        for (int j = 0; j < 64; j++) s += r[j];
        sc[t] = s * 0.125f;   // / sqrt(64)
    }
    __syncthreads();
    if (t < 4) {
        float s0 = sc[t*4], s1 = sc[t*4+1], s2 = sc[t*4+2], s3 = sc[t*4+3];
        float m = fmaxf(fmaxf(s0, s1), fmaxf(s2, s3));
        float e0 = expf(s0 - m), e1 = expf(s1 - m), e2 = expf(s2 - m), e3 = expf(s3 - m);
        float inv = 1.0f / (e0 + e1 + e2 + e3);
        aw[t*4] = e0*inv; aw[t*4+1] = e1*inv; aw[t*4+2] = e2*inv; aw[t*4+3] = e3*inv;
    }
    __syncthreads();
    float c = 0.0f;
#pragma unroll
    for (int n = 0; n < 4; n++) c = fmaf(aw[h * 4 + n], vn[n], c);
    ctx[(size_t)b * 256 + t] = c;
}

// ---------------- kernel: residual + LN1 + FiLM -> cat[:,0:256] -------------------------
__global__ void film_ln_kernel(const float* __restrict__ regime,
                               const float* __restrict__ ln1_g, const float* __restrict__ ln1_b,
                               const float* __restrict__ sg_w,  const float* __restrict__ sg_b,
                               const float* __restrict__ sb_w,  const float* __restrict__ sb_b) {
    int b = blockIdx.x, t = threadIdx.x;
    __shared__ float red[256];
    const float* wt = g_scratch + W_OFF;
    const float* ao = g_scratch + AO_OFF;
    float* cat = g_scratch + CAT_OFF;

    float x = wt[(size_t)b * 1024 + t] + ao[(size_t)b * 256 + t];  // query + attn_out
    red[t] = x; __syncthreads();
    for (int s = 128; s > 0; s >>= 1) { if (t < s) red[t] += red[t + s]; __syncthreads(); }
    float mu = red[0] * (1.0f / 256.0f);
    __syncthreads();
    float xc = x - mu;
    red[t] = xc * xc; __syncthreads();
    for (int s = 128; s > 0; s >>= 1) { if (t < s) red[t] += red[t + s]; __syncthreads(); }
    float rs = rsqrtf(red[0] * (1.0f / 256.0f) + 1e-5f);

    float ent = xc * rs * ln1_g[t] + ln1_b[t];
    float r0 = regime[b*4+0], r1 = regime[b*4+1], r2 = regime[b*4+2], r3 = regime[b*4+3];
    float gm = r0*sg_w[t*4+0] + r1*sg_w[t*4+1] + r2*sg_w[t*4+2] + r3*sg_w[t*4+3] + sg_b[t];
    float bt = r0*sb_w[t*4+0] + r1*sb_w[t*4+1] + r2*sb_w[t*4+2] + r3*sb_w[t*4+3] + sb_b[t];
    cat[(size_t)b * 1024 + t] = ent * (1.0f + gm) + bt;
}

// ---------------- kernel: LN2 on f2-out + alignment head -> d_out ------------------------
__global__ void final_kernel(const float* __restrict__ ln2_g, const float* __restrict__ ln2_b,
                             const float* __restrict__ a2_w,  const float* __restrict__ a2_b,
                             float* __restrict__ out) {
    int b = blockIdx.x, t = threadIdx.x;
    __shared__ float red[256];
    const float* f2  = g_scratch + F2_OFF  + (size_t)b * 512;
    const float* afc = g_scratch + AFC_OFF + (size_t)b * 128;

    float x0 = f2[t], x1 = f2[t + 256];
    red[t] = x0 + x1; __syncthreads();
    for (int s = 128; s > 0; s >>= 1) { if (t < s) red[t] += red[t + s]; __syncthreads(); }
    float mu = red[0] * (1.0f / 512.0f);
    __syncthreads();
    float c0 = x0 - mu, c1 = x1 - mu;
    red[t] = c0 * c0 + c1 * c1; __syncthreads();
    for (int s = 128; s > 0; s >>= 1) { if (t < s) red[t] += red[t + s]; __syncthreads(); }
    float rs = rsqrtf(red[0] * (1.0f / 512.0f) + 1e-5f);
    __syncthreads();

    float* of = out + (size_t)b * 512;
    of[t]       = c0 * rs * ln2_g[t]       + ln2_b[t];
    of[t + 256] = c1 * rs * ln2_g[t + 256] + ln2_b[t + 256];

    // alignment = sigmoid(a . a2_w + a2_b)
    red[t] = (t < 128) ? afc[t] * a2_w[t] : 0.0f;
    __syncthreads();
    for (int s = 128; s > 0; s >>= 1) { if (t < s) red[t] += red[t + s]; __syncthreads(); }
    if (t == 0) {
        float z = red[0] + a2_b[0];
        out[(size_t)B_SZ * 512 + b] = 1.0f / (1.0f + expf(-z));
    }
}

// ---------------- launch ----------------
extern "C" void kernel_launch(void* const* d_in, const int* in_sizes, int n_in,
                              void* d_out, int out_size) {
    const float* w0        = (const float*)d_in[0];
    const float* w1        = (const float*)d_in[1];
    const float* w2        = (const float*)d_in[2];
    const float* w3        = (const float*)d_in[3];
    const float* regime    = (const float*)d_in[4];
    const float* tfw       = (const float*)d_in[5];
    const float* in_proj_w = (const float*)d_in[6];
    const float* in_proj_b = (const float*)d_in[7];
    const float* out_proj_w= (const float*)d_in[8];
    const float* out_proj_b= (const float*)d_in[9];
    const float* ln1_g     = (const float*)d_in[10];
    const float* ln1_b     = (const float*)d_in[11];
    const float* sg_w      = (const float*)d_in[12];
    const float* sg_b      = (const float*)d_in[13];
    const float* sb_w      = (const float*)d_in[14];
    const float* sb_b      = (const float*)d_in[15];
    const float* f1_w      = (const float*)d_in[16];
    const float* f1_b      = (const float*)d_in[17];
    const float* f2_w      = (const float*)d_in[18];
    const float* f2_b      = (const float*)d_in[19];
    const float* ln2_g     = (const float*)d_in[20];
    const float* ln2_b     = (const float*)d_in[21];
    const float* a1_w      = (const float*)d_in[22];
    const float* a1_b      = (const float*)d_in[23];
    const float* a2_w      = (const float*)d_in[24];
    const float* a2_b      = (const float*)d_in[25];

    float* scr = nullptr;
    cudaGetSymbolAddress((void**)&scr, g_scratch);

    // 1) weighted mix (+ cat tails)
    prep_kernel<<<(B_SZ * 64) / 256, 256>>>(w0, w1, w2, w3, tfw);

    // 2) q = weighted[:,0,:] @ wq^T + bq      (M=32768, N=256, K=256, lda=1024)
    sgemm_nt<<<dim3(2, 256), 256>>>(scr + W_OFF, 1024, in_proj_w, in_proj_b,
                                    scr + Q_OFF, 256, 256, 0);
    // 3) kv = weighted_flat @ [wk;wv]^T       (M=131072, N=512, K=256)
    sgemm_nt<<<dim3(4, 1024), 256>>>(scr + W_OFF, 256, in_proj_w + 256 * 256,
                                     in_proj_b + 256, scr + KV_OFF, 512, 256, 0);
    // 4) attention
    attn_kernel<<<B_SZ, 256>>>();
    // 5) attn_out = ctx @ out_proj^T
    sgemm_nt<<<dim3(2, 256), 256>>>(scr + CTX_OFF, 256, out_proj_w, out_proj_b,
                                    scr + AO_OFF, 256, 256, 0);
    // 6) LN1 + FiLM -> cat[:,0:256]
    film_ln_kernel<<<B_SZ, 256>>>(regime, ln1_g, ln1_b, sg_w, sg_b, sb_w, sb_b);
    // 7) h = gelu(cat @ f1^T + b)             (M=32768, N=1024, K=1024)
    sgemm_nt<<<dim3(8, 256), 256>>>(scr + CAT_OFF, 1024, f1_w, f1_b,
                                    scr + H_OFF, 1024, 1024, 1);
    // 8) a = gelu(cat @ a1^T + b)             (N=128, K=1024)
    sgemm_nt<<<dim3(1, 256), 256>>>(scr + CAT_OFF, 1024, a1_w, a1_b,
                                    scr + AFC_OFF, 128, 1024, 1);
    // 9) f2 = h @ f2^T + b                    (N=512, K=1024)
    sgemm_nt<<<dim3(4, 256), 256>>>(scr + H_OFF, 1024, f2_w, f2_b,
                                    scr + F2_OFF, 512, 1024, 0);
    // 10) LN2 + alignment -> d_out
    final_kernel<<<B_SZ, 256>>>(ln2_g, ln2_b, a2_w, a2_b, (float*)d_out);
}

// round 3
// speedup vs baseline: 2.5334x; 2.5334x over previous
#include <cuda_runtime.h>
#include <math.h>
#include <cstdint>

// ---------------- problem constants ----------------
#define B_SZ   32768
#define D_M    256
#define CAT_D  1024

// ---------------- scratch layout (floats) ----------------
#define W_OFF   0ull
#define CAT_OFF 33554432ull
#define Q_OFF   67108864ull
#define KV_OFF  75497472ull
#define CTX_OFF 142606336ull
#define AO_OFF  150994944ull
#define H_OFF   159383552ull
#define AFC_OFF 192937984ull
#define F2_OFF  197132288ull
#define SCR_TOTAL 213909504ull

__device__ float g_scratch[SCR_TOTAL];

__device__ __forceinline__ float gelu_exact(float x) {
    return 0.5f * x * (1.0f + erff(x * 0.70710678118654752440f));
}

__device__ __forceinline__ uint32_t f2tf32(float x) {
    uint32_t r;
    asm("cvt.rna.tf32.f32 %0, %1;" : "=r"(r) : "f"(x));
    return r;
}

// ============ tf32 mma.sync GEMM: C[M,N] = A[M,K(lda)] @ W[N,K]^T + bias ============
// CTA tile 128x128, BK=32, 256 threads = 8 warps (4 x 2), warp tile 32x64.
// Requires M%128==0, N%128==0, K%32==0.
__global__ __launch_bounds__(256) void gemm_mma(
    const float* __restrict__ A, int lda,
    const float* __restrict__ W,
    const float* __restrict__ bias,
    float* __restrict__ C,
    int N, int K, int gelu_epi)
{
    __shared__ float As[128][36];   // [m][k], tf32-rounded bits
    __shared__ float Bs[128][36];   // [n][k]

    const int tid  = threadIdx.x;
    const int wid  = tid >> 5;
    const int lane = tid & 31;
    const size_t bm = (size_t)blockIdx.y * 128;
    const int bn = blockIdx.x * 128;
    const int warp_m = (wid & 3) * 32;   // 0,32,64,96
    const int warp_n = (wid >> 2) * 64;  // 0,64

    float acc[2][8][4];
#pragma unroll
    for (int mt = 0; mt < 2; mt++)
#pragma unroll
        for (int nt = 0; nt < 8; nt++)
#pragma unroll
            for (int f = 0; f < 4; f++) acc[mt][nt][f] = 0.0f;

    const int g = lane >> 2;   // 0..7
    const int tq = lane & 3;   // 0..3

    for (int k0 = 0; k0 < K; k0 += 32) {
        // ---- global -> shared (tf32-rounded), 4 float4 granules per thread per matrix
#pragma unroll
        for (int p = 0; p < 4; p++) {
            int linear = tid + (p << 8);       // 0..1023
            int r  = linear >> 3;              // 0..127
            int kk = (linear & 7) << 2;        // 0..28
            float4 va = *(const float4*)(A + (bm + r) * (size_t)lda + k0 + kk);
            float4 vb = *(const float4*)(W + (size_t)(bn + r) * K + k0 + kk);
            uint4 ua, ub;
            ua.x = f2tf32(va.x); ua.y = f2tf32(va.y); ua.z = f2tf32(va.z); ua.w = f2tf32(va.w);
            ub.x = f2tf32(vb.x); ub.y = f2tf32(vb.y); ub.z = f2tf32(vb.z); ub.w = f2tf32(vb.w);
            *(uint4*)&As[r][kk] = ua;
            *(uint4*)&Bs[r][kk] = ub;
        }
        __syncthreads();

        // ---- compute: 4 k-substeps of 8
#pragma unroll
        for (int ks = 0; ks < 4; ks++) {
            const int kk = ks << 3;
            uint32_t af[2][4];
#pragma unroll
            for (int mt = 0; mt < 2; mt++) {
                const int row = warp_m + mt * 16 + g;
                af[mt][0] = __float_as_uint(As[row    ][kk + tq    ]);
                af[mt][1] = __float_as_uint(As[row + 8][kk + tq    ]);
                af[mt][2] = __float_as_uint(As[row    ][kk + tq + 4]);
                af[mt][3] = __float_as_uint(As[row + 8][kk + tq + 4]);
            }
#pragma unroll
            for (int nt = 0; nt < 8; nt++) {
                const int col = warp_n + nt * 8 + g;
                uint32_t b0 = __float_as_uint(Bs[col][kk + tq    ]);
                uint32_t b1 = __float_as_uint(Bs[col][kk + tq + 4]);
#pragma unroll
                for (int mt = 0; mt < 2; mt++) {
                    asm volatile(
                        "mma.sync.aligned.m16n8k8.row.col.f32.tf32.tf32.f32 "
                        "{%0,%1,%2,%3}, {%4,%5,%6,%7}, {%8,%9}, {%0,%1,%2,%3};"
                        : "+f"(acc[mt][nt][0]), "+f"(acc[mt][nt][1]),
                          "+f"(acc[mt][nt][2]), "+f"(acc[mt][nt][3])
                        : "r"(af[mt][0]), "r"(af[mt][1]), "r"(af[mt][2]), "r"(af[mt][3]),
                          "r"(b0), "r"(b1));
                }
            }
        }
        __syncthreads();
    }

    // ---- epilogue: bias (+gelu), float2 stores
#pragma unroll
    for (int mt = 0; mt < 2; mt++) {
        const size_t row0 = bm + warp_m + mt * 16 + g;
#pragma unroll
        for (int nt = 0; nt < 8; nt++) {
            const int col = bn + warp_n + nt * 8 + tq * 2;
            float bz0 = bias[col], bz1 = bias[col + 1];
            float v0 = acc[mt][nt][0] + bz0;
            float v1 = acc[mt][nt][1] + bz1;
            float v2 = acc[mt][nt][2] + bz0;
            float v3 = acc[mt][nt][3] + bz1;
            if (gelu_epi) {
                v0 = gelu_exact(v0); v1 = gelu_exact(v1);
                v2 = gelu_exact(v2); v3 = gelu_exact(v3);
            }
            float2 o0 = {v0, v1};
            float2 o1 = {v2, v3};
            *(float2*)(C + row0 * (size_t)N + col)       = o0;
            *(float2*)(C + (row0 + 8) * (size_t)N + col) = o1;
        }
    }
}

// ---------------- kernel 1: weighted mix + cat[:,256:1024] ----------------
__global__ void prep_kernel(const float* __restrict__ w0, const float* __restrict__ w1,
                            const float* __restrict__ w2, const float* __restrict__ w3,
                            const float* __restrict__ tfw) {
    float t0 = tfw[0], t1 = tfw[1], t2 = tfw[2], t3 = tfw[3];
    float m = fmaxf(fmaxf(t0, t1), fmaxf(t2, t3));
    float e0 = expf(t0 - m), e1 = expf(t1 - m), e2 = expf(t2 - m), e3 = expf(t3 - m);
    float inv = 1.0f / (e0 + e1 + e2 + e3);
    float s[4] = {e0 * inv, e1 * inv, e2 * inv, e3 * inv};

    int g = blockIdx.x * blockDim.x + threadIdx.x;
    int b = g >> 6;
    int c = (g & 63) << 2;
    const float* ws[4] = {w0, w1, w2, w3};
    float* wt  = g_scratch + W_OFF;
    float* cat = g_scratch + CAT_OFF;
    size_t src = (size_t)b * D_M + c;
#pragma unroll
    for (int n = 0; n < 4; n++) {
        float4 v = *(const float4*)(ws[n] + src);
        v.x *= s[n]; v.y *= s[n]; v.z *= s[n]; v.w *= s[n];
        *(float4*)(wt + ((size_t)(b * 4 + n)) * D_M + c) = v;
        if (n >= 1)
            *(float4*)(cat + (size_t)b * CAT_D + n * D_M + c) = v;
    }
}

// ---------------- tiny 4-token 4-head attention ----------------
__global__ void attn_kernel() {
    const float* q  = g_scratch + Q_OFF;
    const float* kv = g_scratch + KV_OFF;
    float* ctx = g_scratch + CTX_OFF;
    int b = blockIdx.x, t = threadIdx.x, h = t >> 6;
    __shared__ float red[4][256];
    __shared__ float sc[16];
    __shared__ float aw[16];

    float qd = q[(size_t)b * 256 + t];
    const float* kvb = kv + (size_t)b * 2048;
    float vn[4];
#pragma unroll
    for (int n = 0; n < 4; n++) {
        float kn = kvb[n * 512 + t];
        vn[n] = kvb[n * 512 + 256 + t];
        red[n][t] = qd * kn;
    }
    __syncthreads();
    if (t < 16) {
        int hh = t >> 2, n = t & 3;
        float s = 0.0f;
        const float* r = &red[n][hh * 64];
#pragma unroll
        for (int j = 0; j < 64; j++) s += r[j];
        sc[t] = s * 0.125f;
    }
    __syncthreads();
    if (t < 4) {
        float s0 = sc[t*4], s1 = sc[t*4+1], s2 = sc[t*4+2], s3 = sc[t*4+3];
        float m = fmaxf(fmaxf(s0, s1), fmaxf(s2, s3));
        float e0 = expf(s0 - m), e1 = expf(s1 - m), e2 = expf(s2 - m), e3 = expf(s3 - m);
        float inv = 1.0f / (e0 + e1 + e2 + e3);
        aw[t*4] = e0*inv; aw[t*4+1] = e1*inv; aw[t*4+2] = e2*inv; aw[t*4+3] = e3*inv;
    }
    __syncthreads();
    float c = 0.0f;
#pragma unroll
    for (int n = 0; n < 4; n++) c = fmaf(aw[h * 4 + n], vn[n], c);
    ctx[(size_t)b * 256 + t] = c;
}

// ---------------- residual + LN1 + FiLM -> cat[:,0:256] ----------------
__global__ void film_ln_kernel(const float* __restrict__ regime,
                               const float* __restrict__ ln1_g, const float* __restrict__ ln1_b,
                               const float* __restrict__ sg_w,  const float* __restrict__ sg_b,
                               const float* __restrict__ sb_w,  const float* __restrict__ sb_b) {
    int b = blockIdx.x, t = threadIdx.x;
    __shared__ float red[256];
    const float* wt = g_scratch + W_OFF;
    const float* ao = g_scratch + AO_OFF;
    float* cat = g_scratch + CAT_OFF;

    float x = wt[(size_t)b * 1024 + t] + ao[(size_t)b * 256 + t];
    red[t] = x; __syncthreads();
    for (int s = 128; s > 0; s >>= 1) { if (t < s) red[t] += red[t + s]; __syncthreads(); }
    float mu = red[0] * (1.0f / 256.0f);
    __syncthreads();
    float xc = x - mu;
    red[t] = xc * xc; __syncthreads();
    for (int s = 128; s > 0; s >>= 1) { if (t < s) red[t] += red[t + s]; __syncthreads(); }
    float rs = rsqrtf(red[0] * (1.0f / 256.0f) + 1e-5f);

    float ent = xc * rs * ln1_g[t] + ln1_b[t];
    float r0 = regime[b*4+0], r1 = regime[b*4+1], r2 = regime[b*4+2], r3 = regime[b*4+3];
    float gm = r0*sg_w[t*4+0] + r1*sg_w[t*4+1] + r2*sg_w[t*4+2] + r3*sg_w[t*4+3] + sg_b[t];
    float bt = r0*sb_w[t*4+0] + r1*sb_w[t*4+1] + r2*sb_w[t*4+2] + r3*sb_w[t*4+3] + sb_b[t];
    cat[(size_t)b * 1024 + t] = ent * (1.0f + gm) + bt;
}

// ---------------- LN2 + alignment head -> d_out ----------------
__global__ void final_kernel(const float* __restrict__ ln2_g, const float* __restrict__ ln2_b,
                             const float* __restrict__ a2_w,  const float* __restrict__ a2_b,
                             float* __restrict__ out) {
    int b = blockIdx.x, t = threadIdx.x;
    __shared__ float red[256];
    const float* f2  = g_scratch + F2_OFF  + (size_t)b * 512;
    const float* afc = g_scratch + AFC_OFF + (size_t)b * 128;

    float x0 = f2[t], x1 = f2[t + 256];
    red[t] = x0 + x1; __syncthreads();
    for (int s = 128; s > 0; s >>= 1) { if (t < s) red[t] += red[t + s]; __syncthreads(); }
    float mu = red[0] * (1.0f / 512.0f);
    __syncthreads();
    float c0 = x0 - mu, c1 = x1 - mu;
    red[t] = c0 * c0 + c1 * c1; __syncthreads();
    for (int s = 128; s > 0; s >>= 1) { if (t < s) red[t] += red[t + s]; __syncthreads(); }
    float rs = rsqrtf(red[0] * (1.0f / 512.0f) + 1e-5f);
    __syncthreads();

    float* of = out + (size_t)b * 512;
    of[t]       = c0 * rs * ln2_g[t]       + ln2_b[t];
    of[t + 256] = c1 * rs * ln2_g[t + 256] + ln2_b[t + 256];

    red[t] = (t < 128) ? afc[t] * a2_w[t] : 0.0f;
    __syncthreads();
    for (int s = 128; s > 0; s >>= 1) { if (t < s) red[t] += red[t + s]; __syncthreads(); }
    if (t == 0) {
        float z = red[0] + a2_b[0];
        out[(size_t)B_SZ * 512 + b] = 1.0f / (1.0f + expf(-z));
    }
}

// ---------------- launch ----------------
extern "C" void kernel_launch(void* const* d_in, const int* in_sizes, int n_in,
                              void* d_out, int out_size) {
    const float* w0        = (const float*)d_in[0];
    const float* w1        = (const float*)d_in[1];
    const float* w2        = (const float*)d_in[2];
    const float* w3        = (const float*)d_in[3];
    const float* regime    = (const float*)d_in[4];
    const float* tfw       = (const float*)d_in[5];
    const float* in_proj_w = (const float*)d_in[6];
    const float* in_proj_b = (const float*)d_in[7];
    const float* out_proj_w= (const float*)d_in[8];
    const float* out_proj_b= (const float*)d_in[9];
    const float* ln1_g     = (const float*)d_in[10];
    const float* ln1_b     = (const float*)d_in[11];
    const float* sg_w      = (const float*)d_in[12];
    const float* sg_b      = (const float*)d_in[13];
    const float* sb_w      = (const float*)d_in[14];
    const float* sb_b      = (const float*)d_in[15];
    const float* f1_w      = (const float*)d_in[16];
    const float* f1_b      = (const float*)d_in[17];
    const float* f2_w      = (const float*)d_in[18];
    const float* f2_b      = (const float*)d_in[19];
    const float* ln2_g     = (const float*)d_in[20];
    const float* ln2_b     = (const float*)d_in[21];
    const float* a1_w      = (const float*)d_in[22];
    const float* a1_b      = (const float*)d_in[23];
    const float* a2_w      = (const float*)d_in[24];
    const float* a2_b      = (const float*)d_in[25];

    float* scr = nullptr;
    cudaGetSymbolAddress((void**)&scr, g_scratch);

    // 1) weighted mix (+ cat tails)
    prep_kernel<<<(B_SZ * 64) / 256, 256>>>(w0, w1, w2, w3, tfw);

    // 2) q = weighted[:,0,:] @ wq^T + bq      (M=32768, N=256, K=256, lda=1024)
    gemm_mma<<<dim3(2, 256), 256>>>(scr + W_OFF, 1024, in_proj_w, in_proj_b,
                                    scr + Q_OFF, 256, 256, 0);
    // 3) kv = weighted_flat @ [wk;wv]^T       (M=131072, N=512, K=256)
    gemm_mma<<<dim3(4, 1024), 256>>>(scr + W_OFF, 256, in_proj_w + 256 * 256,
                                     in_proj_b + 256, scr + KV_OFF, 512, 256, 0);
    // 4) attention
    attn_kernel<<<B_SZ, 256>>>();
    // 5) attn_out = ctx @ out_proj^T          (N=256, K=256)
    gemm_mma<<<dim3(2, 256), 256>>>(scr + CTX_OFF, 256, out_proj_w, out_proj_b,
                                    scr + AO_OFF, 256, 256, 0);
    // 6) LN1 + FiLM -> cat[:,0:256]
    film_ln_kernel<<<B_SZ, 256>>>(regime, ln1_g, ln1_b, sg_w, sg_b, sb_w, sb_b);
    // 7) h = gelu(cat @ f1^T + b)             (N=1024, K=1024)
    gemm_mma<<<dim3(8, 256), 256>>>(scr + CAT_OFF, 1024, f1_w, f1_b,
                                    scr + H_OFF, 1024, 1024, 1);
    // 8) a = gelu(cat @ a1^T + b)             (N=128, K=1024)
    gemm_mma<<<dim3(1, 256), 256>>>(scr + CAT_OFF, 1024, a1_w, a1_b,
                                    scr + AFC_OFF, 128, 1024, 1);
    // 9) f2 = h @ f2^T + b                    (N=512, K=1024)
    gemm_mma<<<dim3(4, 256), 256>>>(scr + H_OFF, 1024, f2_w, f2_b,
                                    scr + F2_OFF, 512, 1024, 0);
    // 10) LN2 + alignment -> d_out
    final_kernel<<<B_SZ, 256>>>(ln2_g, ln2_b, a2_w, a2_b, (float*)d_out);
}